// round 12
// baseline (speedup 1.0000x reference)
#include <cuda_runtime.h>
#include <math.h>

#define E_TOTAL 400000
#define NNODES  12500
#define T1      256     // edges per tile, kernel 1
#define NTILES  ((E_TOTAL + T1 - 1) / T1)
#define PH      66      // smem row pitch (floats)
#define FULLC   25
#define MALL    19
#define NSPEC   90

typedef unsigned long long ull;

// scratch (static device globals; no allocation in kernel_launch)
__device__ float F_buf[(size_t)E_TOTAL * 320];
__device__ int   d_cnt[NNODES];      // zero-initialized; re-zeroed by wigner_gather
__device__ int   d_cur[NNODES];      // zero-initialized; re-zeroed by wigner_gather
__device__ int   d_offs[NNODES + 1];
__device__ int   d_eids[E_TOTAL];
__device__ float SPb[NSPEC * 64];    // semb @ W1[128:192] + b1
__device__ float RPb[NSPEC * 64];    // remb @ W1[192:256]

__device__ __forceinline__ ull pack2(float x) {
    ull r; asm("mov.b64 %0,{%1,%1};" : "=l"(r) : "f"(x)); return r;
}
__device__ __forceinline__ ull pack2xy(float x, float y) {
    ull r; asm("mov.b64 %0,{%1,%2};" : "=l"(r) : "f"(x), "f"(y)); return r;
}
__device__ __forceinline__ void fma2(ull& d, ull a, ull b) {
    asm("fma.rn.f32x2 %0,%1,%2,%0;" : "+l"(d) : "l"(a), "l"(b));
}
__device__ __forceinline__ float2 unpk(ull v) {
    float2 o; asm("mov.b64 {%0,%1},%2;" : "=f"(o.x), "=f"(o.y) : "l"(v)); return o;
}

// permuted float4 slot within a 64-float W row (conflict-free b-loads)
__device__ __forceinline__ int wperm(int c4) { return ((c4 & 1) << 3) | (c4 >> 1); }

// ------------------------- fused prelude: species projection + histogram
__global__ void prep_kernel(const int* __restrict__ receivers,
                            const float* __restrict__ semb,
                            const float* __restrict__ remb,
                            const float* __restrict__ W1,
                            const float* __restrict__ b1)
{
    const int SPBLK = (NSPEC * 64 + 255) / 256;   // 23 blocks of species work
    if (blockIdx.x < SPBLK) {
        int idx = blockIdx.x * 256 + threadIdx.x;
        if (idx < NSPEC * 64) {
            int s = idx >> 6, c = idx & 63;
            float sp = b1[c], rp = 0.0f;
            #pragma unroll 8
            for (int k = 0; k < 64; ++k) {
                sp += semb[s * 64 + k] * W1[(128 + k) * 64 + c];
                rp += remb[s * 64 + k] * W1[(192 + k) * 64 + c];
            }
            SPb[idx] = sp;
            RPb[idx] = rp;
        }
    } else {
        int e = (blockIdx.x - SPBLK) * 256 + threadIdx.x;
        if (e < E_TOTAL) atomicAdd(&d_cnt[receivers[e]], 1);
    }
}
__global__ void scan_kernel() {
    __shared__ int s[1024];
    const int CH = (NNODES + 1023) / 1024;   // 13
    int t = threadIdx.x;
    int base = t * CH;
    int loc[CH];
    int sum = 0;
    #pragma unroll
    for (int i = 0; i < CH; ++i) {
        int v = (base + i < NNODES) ? d_cnt[base + i] : 0;
        loc[i] = sum; sum += v;
    }
    s[t] = sum;
    __syncthreads();
    for (int off = 1; off < 1024; off <<= 1) {
        int v = s[t];
        int u = (t >= off) ? s[t - off] : 0;
        __syncthreads();
        s[t] = v + u;
        __syncthreads();
    }
    int excl = (t > 0) ? s[t - 1] : 0;
    #pragma unroll
    for (int i = 0; i < CH; ++i)
        if (base + i < NNODES) d_offs[base + i] = excl + loc[i];
    if (t == 1023) d_offs[NNODES] = s[1023];
}
__global__ void fill_kernel(const int* __restrict__ receivers) {
    int e = blockIdx.x * blockDim.x + threadIdx.x;
    if (e < E_TOTAL) {
        int r = receivers[e];
        int pos = atomicAdd(&d_cur[r], 1);
        d_eids[d_offs[r] + pos] = e;
    }
}

// ---------------------------------------------------------------- MLP GEMM
// 8 rows x 8 cols per thread; 256 threads cover 256 rows x 64 cols.
__device__ __forceinline__ void gemm64(const float* __restrict__ As,
                                       const ull*  __restrict__ Wp,
                                       int row0, int cj, ull acc[32])
{
    #pragma unroll 4
    for (int k2 = 0; k2 < 32; ++k2) {
        float2 a8[8];
        #pragma unroll
        for (int r = 0; r < 8; ++r)
            a8[r] = *(const float2*)(As + (row0 + r) * PH + 2 * k2);
        #pragma unroll
        for (int kk = 0; kk < 2; ++kk) {
            int k = 2 * k2 + kk;
            ulonglong2 bA = *(const ulonglong2*)(Wp + k * 32 + cj * 2);
            ulonglong2 bB = *(const ulonglong2*)(Wp + k * 32 + 16 + cj * 2);
            #pragma unroll
            for (int r = 0; r < 8; ++r) {
                ull p = pack2(kk ? a8[r].y : a8[r].x);
                fma2(acc[r * 4 + 0], p, bA.x);
                fma2(acc[r * 4 + 1], p, bA.y);
                fma2(acc[r * 4 + 2], p, bB.x);
                fma2(acc[r * 4 + 3], p, bB.y);
            }
        }
    }
}

// In-register LayerNorm + SiLU over 8 rows x 8 cols (row spread across 8 lanes,
// cj = lane&7, shuffle masks 1/2/4), then float2-store rows to smem tile
// (PH=66 -> odd rows are only 8B aligned; float4 stores would fault).
__device__ __forceinline__ void ln_silu_reg_store(ull acc[32], float* __restrict__ H,
                                                  int row0, int cj,
                                                  const float* __restrict__ g,
                                                  const float* __restrict__ be,
                                                  const float* __restrict__ bias)
{
    float4 gl = ((const float4*)g)[cj * 2];
    float4 gh = ((const float4*)g)[cj * 2 + 1];
    float4 el = ((const float4*)be)[cj * 2];
    float4 eh = ((const float4*)be)[cj * 2 + 1];
    float4 bl = make_float4(0, 0, 0, 0), bh = bl;
    if (bias) {
        bl = ((const float4*)bias)[cj * 2];
        bh = ((const float4*)bias)[cj * 2 + 1];
    }
    float gv[8] = {gl.x, gl.y, gl.z, gl.w, gh.x, gh.y, gh.z, gh.w};
    float ev[8] = {el.x, el.y, el.z, el.w, eh.x, eh.y, eh.z, eh.w};
    #pragma unroll
    for (int r = 0; r < 8; ++r) {
        float2 e0 = unpk(acc[4*r+0]); float2 e1 = unpk(acc[4*r+1]);
        float2 e2 = unpk(acc[4*r+2]); float2 e3 = unpk(acc[4*r+3]);
        float v[8] = { e0.x + bl.x, e0.y + bl.y, e1.x + bl.z, e1.y + bl.w,
                       e2.x + bh.x, e2.y + bh.y, e3.x + bh.z, e3.y + bh.w };
        float s = 0.0f, s2 = 0.0f;
        #pragma unroll
        for (int j = 0; j < 8; ++j) { s += v[j]; s2 += v[j] * v[j]; }
        #pragma unroll
        for (int o = 4; o > 0; o >>= 1) {
            s  += __shfl_xor_sync(0xffffffffu, s,  o);
            s2 += __shfl_xor_sync(0xffffffffu, s2, o);
        }
        float mu  = s * (1.0f / 64.0f);
        float var = s2 * (1.0f / 64.0f) - mu * mu;
        float rs  = rsqrtf(fmaxf(var, 0.0f) + 1e-5f);
        #pragma unroll
        for (int j = 0; j < 8; ++j) {
            float x = (v[j] - mu) * rs * gv[j] + ev[j];
            v[j] = x / (1.0f + __expf(-x));
        }
        float* p = H + (row0 + r) * PH + cj * 8;
        *(float2*)(p)     = make_float2(v[0], v[1]);
        *(float2*)(p + 2) = make_float2(v[2], v[3]);
        *(float2*)(p + 4) = make_float2(v[4], v[5]);
        *(float2*)(p + 6) = make_float2(v[6], v[7]);
    }
}

// load one 64x64 W chunk into a permuted smem slot (256 threads)
__device__ __forceinline__ void ldW(float* __restrict__ Wslot,
                                    const float* __restrict__ Wsrc, int tid,
                                    int src_row_pitch_f4)
{
    #pragma unroll
    for (int q = 0; q < 4; ++q) {
        int lin = tid + 256 * q;
        int k = lin >> 4, c4 = lin & 15;
        ((float4*)Wslot)[k * 16 + wperm(c4)] =
            ((const float4*)Wsrc)[k * src_row_pitch_f4 + c4];
    }
}

// smem: tile buffer + 2 W slots + species idx
#define SM1_FLOATS (T1 * PH + 2 * 64 * 64 + 64)
#define SM1_BYTES  (SM1_FLOATS * 4 + 2048 + 1024)

__global__ __launch_bounds__(256, 2)
void mlp_kernel(const int*   __restrict__ species,
                const float* __restrict__ dist,
                const int*   __restrict__ senders,
                const int*   __restrict__ receivers,
                const float* __restrict__ W1,
                const float* __restrict__ g1, const float* __restrict__ be1,
                const float* __restrict__ W2, const float* __restrict__ b2,
                const float* __restrict__ g2, const float* __restrict__ be2,
                const float* __restrict__ W3, const float* __restrict__ b3)
{
    extern __shared__ float sm[];
    float* Xc  = sm;                        // X chunk -> H1 -> H2
    float* Ws0 = Xc + T1 * PH;
    float* Ws1 = Ws0 + 64 * 64;
    int*   spS = (int*)(Ws1 + 64 * 64 + 64);
    int*   spR = spS + T1;

    const int tid  = threadIdx.x;           // 0..255
    const int cj   = tid & 7;
    const int ri   = tid >> 3;
    const int row0 = 8 * ri;

    // persistent: loop over edge tiles
    for (int t = blockIdx.x; t < NTILES; t += gridDim.x) {
        const int base = t * T1;
        __syncthreads();                    // prior tile's readers done

        {
            int eg = base + tid;
            if (eg >= E_TOTAL) eg = E_TOTAL - 1;
            spS[tid] = species[senders[eg]];
            spR[tid] = species[receivers[eg]];
        }

        // preload both W1 chunks + X chunk 0
        ldW(Ws0, W1, tid, 16);
        ldW(Ws1, W1 + 64 * 64, tid, 16);
        #pragma unroll
        for (int q = 0; q < 32; ++q) {
            int lin = tid + 256 * q;
            int row = lin >> 5, c2 = lin & 31;
            int eg = base + row;
            if (eg >= E_TOTAL) eg = E_TOTAL - 1;
            float2 v = ((const float2*)dist)[(size_t)eg * 64 + c2];
            *(float2*)(Xc + row * PH + c2 * 2) = v;
        }
        __syncthreads();

        // ---- stage 1 acc init from precomputed species projections (incl. b1)
        ull acc[32];
        #pragma unroll
        for (int r = 0; r < 8; ++r) {
            int row = row0 + r;
            int ss = spS[row], sr = spR[row];
            float4 u0 = ((const float4*)SPb)[ss * 16 + cj * 2];
            float4 u1 = ((const float4*)SPb)[ss * 16 + cj * 2 + 1];
            float4 v0 = ((const float4*)RPb)[sr * 16 + cj * 2];
            float4 v1 = ((const float4*)RPb)[sr * 16 + cj * 2 + 1];
            acc[4*r+0] = pack2xy(u0.x + v0.x, u0.y + v0.y);
            acc[4*r+1] = pack2xy(u0.z + v0.z, u0.w + v0.w);
            acc[4*r+2] = pack2xy(u1.x + v1.x, u1.y + v1.y);
            acc[4*r+3] = pack2xy(u1.z + v1.z, u1.w + v1.w);
        }

        // ---- stage 1: += dist @ W1 (chunk 0 then chunk 1)
        gemm64(Xc, (const ull*)Ws0, row0, cj, acc);
        __syncthreads();
        #pragma unroll
        for (int q = 0; q < 32; ++q) {
            int lin = tid + 256 * q;
            int row = lin >> 5, c2 = lin & 31;
            int eg = base + row;
            if (eg >= E_TOTAL) eg = E_TOTAL - 1;
            float2 v = ((const float2*)dist)[(size_t)eg * 64 + 32 + c2];
            *(float2*)(Xc + row * PH + c2 * 2) = v;
        }
        __syncthreads();
        gemm64(Xc, (const ull*)Ws1, row0, cj, acc);
        __syncthreads();            // all gemms done before H1 overwrites Xc

        // ---- E1: in-reg LN+SiLU -> H1 in Xc; prefetch W2 into Ws0
        ln_silu_reg_store(acc, Xc, row0, cj, g1, be1, nullptr);
        ldW(Ws0, W2, tid, 16);
        __syncthreads();

        // ---- stage 2: H2 = H1 @ W2
        #pragma unroll
        for (int i = 0; i < 32; ++i) acc[i] = 0ull;
        gemm64(Xc, (const ull*)Ws0, row0, cj, acc);
        __syncthreads();            // all reads of H1 done before H2 overwrites

        // ---- E2: +b2, LN+SiLU -> H2 in Xc; prefetch W3 m=0 into Ws1
        ln_silu_reg_store(acc, Xc, row0, cj, g2, be2, b2);
        ldW(Ws1, W3, tid, 80);
        __syncthreads();

        // ---- stage 3: F_m = H2 @ W3[:, 64m:64m+64] + b3 -> F_buf
        for (int m = 0; m < 5; ++m) {
            const float* Wcur = (m & 1) ? Ws0 : Ws1;
            #pragma unroll
            for (int i = 0; i < 32; ++i) acc[i] = 0ull;
            gemm64(Xc, (const ull*)Wcur, row0, cj, acc);

            float4 bl = ((const float4*)b3)[m * 16 + cj * 2];
            float4 bh = ((const float4*)b3)[m * 16 + cj * 2 + 1];
            #pragma unroll
            for (int r = 0; r < 8; ++r) {
                int eg = base + row0 + r;
                if (eg >= E_TOTAL) continue;
                float2 e0 = unpk(acc[4*r+0]); float2 e1 = unpk(acc[4*r+1]);
                float2 e2 = unpk(acc[4*r+2]); float2 e3 = unpk(acc[4*r+3]);
                float* p = F_buf + (size_t)eg * 320 + m * 64 + cj * 8;
                *(float4*)(p)     = make_float4(e0.x + bl.x, e0.y + bl.y, e1.x + bl.z, e1.y + bl.w);
                *(float4*)(p + 4) = make_float4(e2.x + bh.x, e2.y + bh.y, e3.x + bh.z, e3.y + bh.w);
            }
            if (m < 4) {
                // next chunk starts at column (m+1)*64 floats
                ldW((m & 1) ? Ws1 : Ws0, W3 + (m + 1) * 64, tid, 80);
                __syncthreads();
            }
        }
    }
}

// --------------------------------- kernel 2: gather per node, no atomics,
// with register prefetch of the NEXT edge's wig/F/env before computing current.
__global__ __launch_bounds__(256)
void wigner_gather(const float* __restrict__ wig,
                   const float* __restrict__ env,
                   float* __restrict__ out)
{
    __shared__ ull wbp[8][25 * 8];
    const int tid  = threadIdx.x;
    const int lane = tid & 31;
    const int warp = tid >> 5;
    const int node = blockIdx.x * 8 + warp;
    if (node >= NNODES) return;

    ull acc[FULLC];
    #pragma unroll
    for (int f = 0; f < FULLC; ++f) acc[f] = 0ull;

    const int beg = d_offs[node];
    const int end = d_offs[node + 1];
    ull* wp = wbp[warp];

    const int f0 = (lane +  0) / 5,  m0 = (lane +  0) - 5 * f0;
    const int f1 = (lane + 32) / 5,  m1 = (lane + 32) - 5 * f1;
    const int f2 = (lane + 64) / 5,  m2 = (lane + 64) - 5 * f2;
    const int f3 = (lane + 96) / 5,  m3 = (lane + 96) - 5 * f3;   // valid if lane < 29

    float wrv0 = 0, wrv1 = 0, wrv2 = 0, wrv3 = 0, scv = 0;
    ull fr[5] = {0, 0, 0, 0, 0};

    auto load_raw = [&](int e) {
        scv = env[e] * 0.2f;
        const float* wr = wig + (size_t)e * (FULLC * MALL);
        wrv0 = wr[f0 * MALL + m0];
        wrv1 = wr[f1 * MALL + m1];
        wrv2 = wr[f2 * MALL + m2];
        if (lane < 29) wrv3 = wr[f3 * MALL + m3];
        const ull* fp = (const ull*)(F_buf + (size_t)e * 320 + 2 * lane);
        fr[0] = fp[0]; fr[1] = fp[32]; fr[2] = fp[64]; fr[3] = fp[96]; fr[4] = fp[128];
    };

    if (beg < end) load_raw(d_eids[beg]);

    for (int idx = beg; idx < end; ++idx) {
        wp[f0 * 8 + m0] = pack2(wrv0 * scv);
        wp[f1 * 8 + m1] = pack2(wrv1 * scv);
        wp[f2 * 8 + m2] = pack2(wrv2 * scv);
        if (lane < 29) wp[f3 * 8 + m3] = pack2(wrv3 * scv);
        ull fc0 = fr[0], fc1 = fr[1], fc2 = fr[2], fc3 = fr[3], fc4 = fr[4];
        __syncwarp();

        if (idx + 1 < end) load_raw(d_eids[idx + 1]);

        #pragma unroll
        for (int f = 0; f < FULLC; ++f) {
            ulonglong2 wA = *(const ulonglong2*)(wp + f * 8);
            ulonglong2 wB = *(const ulonglong2*)(wp + f * 8 + 2);
            ull w4 = wp[f * 8 + 4];
            ull r = acc[f];
            fma2(r, wA.x, fc0);
            fma2(r, wA.y, fc1);
            fma2(r, wB.x, fc2);
            fma2(r, wB.y, fc3);
            fma2(r, w4,   fc4);
            acc[f] = r;
        }
        __syncwarp();
    }

    float* ob = out + (size_t)node * 1600 + 2 * lane;
    #pragma unroll
    for (int f = 0; f < FULLC; ++f) {
        float2 rv = unpk(acc[f]);
        *(float2*)(ob + f * 64) = rv;
    }

    // leave CSR counters zeroed for the next launch (replaces zero_kernel)
    if (lane == 0) { d_cnt[node] = 0; d_cur[node] = 0; }
}

extern "C" void kernel_launch(void* const* d_in, const int* in_sizes, int n_in,
                              void* d_out, int out_size)
{
    const int*   species   = (const int*)  d_in[0];
    const float* dist      = (const float*)d_in[1];
    const int*   senders   = (const int*)  d_in[2];
    const int*   receivers = (const int*)  d_in[3];
    const float* wig       = (const float*)d_in[4];
    const float* env       = (const float*)d_in[5];
    const float* semb      = (const float*)d_in[6];
    const float* remb      = (const float*)d_in[7];
    const float* W1  = (const float*)d_in[8];
    const float* b1  = (const float*)d_in[9];
    const float* g1  = (const float*)d_in[10];
    const float* be1 = (const float*)d_in[11];
    const float* W2  = (const float*)d_in[12];
    const float* b2  = (const float*)d_in[13];
    const float* g2  = (const float*)d_in[14];
    const float* be2 = (const float*)d_in[15];
    const float* W3  = (const float*)d_in[16];
    const float* b3  = (const float*)d_in[17];
    float* out = (float*)d_out;

    int nsm = 148;
    cudaDeviceGetAttribute(&nsm, cudaDevAttrMultiProcessorCount, 0);

    cudaFuncSetAttribute(mlp_kernel,
                         cudaFuncAttributeMaxDynamicSharedMemorySize, SM1_BYTES);

    const int SPBLK = (NSPEC * 64 + 255) / 256;
    prep_kernel<<<SPBLK + (E_TOTAL + 255) / 256, 256>>>(receivers, semb, remb, W1, b1);
    scan_kernel<<<1, 1024>>>();
    fill_kernel<<<(E_TOTAL + 255) / 256, 256>>>(receivers);
    mlp_kernel<<<2 * nsm, 256, SM1_BYTES>>>(
        species, dist, senders, receivers,
        W1, g1, be1, W2, b2, g2, be2, W3, b3);
    wigner_gather<<<(NNODES + 7) / 8, 256>>>(wig, env, out);
}

// round 13
// speedup vs baseline: 1.3673x; 1.3673x over previous
#include <cuda_runtime.h>
#include <cuda_bf16.h>
#include <math.h>

#define E_TOTAL 400000
#define NNODES  12500
#define T1      128
#define NTILES  3125        // 400000 / 128 exactly
#define FULLC   25
#define MALL    19
#define NSPEC   90

typedef unsigned long long ull;
typedef unsigned int u32;

// ---------------- device scratch (static, no allocs)
__device__ float F_buf[(size_t)E_TOTAL * 320];
__device__ int   d_cnt[NNODES];      // zeroed; re-zeroed by wigner_gather
__device__ int   d_cur[NNODES];
__device__ int   d_offs[NNODES + 1];
__device__ int   d_eids[E_TOTAL];
__device__ float SPb[NSPEC * 64];    // semb @ W1[128:192] + b1
__device__ float RPb[NSPEC * 64];    // remb @ W1[192:256]
// split-bf16 weight image: [chunk][hi/lo][n=64][k=64]; chunks: W1c0,W1c1,W2,W3m0..4
__device__ __align__(16) __nv_bfloat16 Bimg[8][2][64 * 64];

// ---------------- f32x2 helpers (wigner kernel)
__device__ __forceinline__ ull pack2(float x) {
    ull r; asm("mov.b64 %0,{%1,%1};" : "=l"(r) : "f"(x)); return r;
}
__device__ __forceinline__ void fma2(ull& d, ull a, ull b) {
    asm("fma.rn.f32x2 %0,%1,%2,%0;" : "+l"(d) : "l"(a), "l"(b));
}
__device__ __forceinline__ float2 unpk(ull v) {
    float2 o; asm("mov.b64 {%0,%1},%2;" : "=f"(o.x), "=f"(o.y) : "l"(v)); return o;
}

// ---------------- HMMA helpers
__device__ __forceinline__ void hmma(float& d0, float& d1, float& d2, float& d3,
                                     u32 a0, u32 a1, u32 a2, u32 a3,
                                     u32 b0, u32 b1) {
    asm volatile("mma.sync.aligned.m16n8k16.row.col.f32.bf16.bf16.f32 "
        "{%0,%1,%2,%3}, {%4,%5,%6,%7}, {%8,%9}, {%0,%1,%2,%3};"
        : "+f"(d0), "+f"(d1), "+f"(d2), "+f"(d3)
        : "r"(a0), "r"(a1), "r"(a2), "r"(a3), "r"(b0), "r"(b1));
}
__device__ __forceinline__ void split2(float x, float y, u32& hi, u32& lo) {
    __nv_bfloat16 hx = __float2bfloat16(x);
    __nv_bfloat16 hy = __float2bfloat16(y);
    __nv_bfloat16 lx = __float2bfloat16(x - __bfloat162float(hx));
    __nv_bfloat16 ly = __float2bfloat16(y - __bfloat162float(hy));
    hi = (u32)__bfloat16_as_ushort(hx) | ((u32)__bfloat16_as_ushort(hy) << 16);
    lo = (u32)__bfloat16_as_ushort(lx) | ((u32)__bfloat16_as_ushort(ly) << 16);
}

// ---------------- prelude: species projection + histogram (fused)
__global__ void prep_kernel(const int* __restrict__ receivers,
                            const float* __restrict__ semb,
                            const float* __restrict__ remb,
                            const float* __restrict__ W1,
                            const float* __restrict__ b1)
{
    const int SPBLK = (NSPEC * 64 + 255) / 256;
    if (blockIdx.x < SPBLK) {
        int idx = blockIdx.x * 256 + threadIdx.x;
        if (idx < NSPEC * 64) {
            int s = idx >> 6, c = idx & 63;
            float sp = b1[c], rp = 0.0f;
            #pragma unroll 8
            for (int k = 0; k < 64; ++k) {
                sp += semb[s * 64 + k] * W1[(128 + k) * 64 + c];
                rp += remb[s * 64 + k] * W1[(192 + k) * 64 + c];
            }
            SPb[idx] = sp;
            RPb[idx] = rp;
        }
    } else {
        int e = (blockIdx.x - SPBLK) * 256 + threadIdx.x;
        if (e < E_TOTAL) atomicAdd(&d_cnt[receivers[e]], 1);
    }
}
__global__ void scan_kernel() {
    __shared__ int s[1024];
    const int CH = (NNODES + 1023) / 1024;
    int t = threadIdx.x;
    int base = t * CH;
    int loc[CH];
    int sum = 0;
    #pragma unroll
    for (int i = 0; i < CH; ++i) {
        int v = (base + i < NNODES) ? d_cnt[base + i] : 0;
        loc[i] = sum; sum += v;
    }
    s[t] = sum;
    __syncthreads();
    for (int off = 1; off < 1024; off <<= 1) {
        int v = s[t];
        int u = (t >= off) ? s[t - off] : 0;
        __syncthreads();
        s[t] = v + u;
        __syncthreads();
    }
    int excl = (t > 0) ? s[t - 1] : 0;
    #pragma unroll
    for (int i = 0; i < CH; ++i)
        if (base + i < NNODES) d_offs[base + i] = excl + loc[i];
    if (t == 1023) d_offs[NNODES] = s[1023];
}
__global__ void fill_kernel(const int* __restrict__ receivers) {
    int e = blockIdx.x * blockDim.x + threadIdx.x;
    if (e < E_TOTAL) {
        int r = receivers[e];
        int pos = atomicAdd(&d_cur[r], 1);
        d_eids[d_offs[r] + pos] = e;
    }
}

// ---------------- weight image: transpose + hi/lo split
__global__ void bprep_kernel(const float* __restrict__ W1,
                             const float* __restrict__ W2,
                             const float* __restrict__ W3)
{
    int c = blockIdx.x;
    for (int idx = threadIdx.x; idx < 4096; idx += blockDim.x) {
        int n = idx >> 6, k = idx & 63;
        float v;
        if (c < 2)       v = W1[(c * 64 + k) * 64 + n];
        else if (c == 2) v = W2[k * 64 + n];
        else             v = W3[k * 320 + (c - 3) * 64 + n];
        __nv_bfloat16 h = __float2bfloat16(v);
        __nv_bfloat16 l = __float2bfloat16(v - __bfloat162float(h));
        Bimg[c][0][n * 64 + k] = h;
        Bimg[c][1][n * 64 + k] = l;
    }
}

// ---------------- MLP (HMMA)
// smem bytes: A hi [128][72]bf16 @0, A lo @18432, Bslot0 @36864 (hi, lo@+9216),
//             Bslot1 @55296, spS @73728, spR @74240
#define AS_HI 0
#define AS_LO 18432
#define BSL0  36864
#define BSL1  55296
#define SPS_O 73728
#define SPR_O 74240
#define SMB   74752

__device__ __forceinline__ void copyB(char* sm_, int slot, int chunk, int tid) {
    const uint4* s0 = (const uint4*)&Bimg[chunk][0][0];
    const uint4* s1 = (const uint4*)&Bimg[chunk][1][0];
    #pragma unroll
    for (int i = 0; i < 2; ++i) {
        int lin = tid + 256 * i;            // 512 uint4 per half
        int n = lin >> 3, kq = lin & 7;
        *(uint4*)(sm_ + slot        + n * 144 + kq * 16) = s0[lin];
        *(uint4*)(sm_ + slot + 9216 + n * 144 + kq * 16) = s1[lin];
    }
}

// X chunk (k: 64*ch..64*ch+63) -> split bf16 into A tiles
__device__ __forceinline__ void splitX(char* sm_, const float4* __restrict__ dp,
                                       int base, int tid, int ch) {
    int row = tid >> 1, h = tid & 1;
    #pragma unroll
    for (int j = 0; j < 8; ++j) {
        float4 v = dp[(size_t)(base + row) * 32 + ch * 16 + h * 8 + j];
        u32 h0, l0, h1, l1;
        split2(v.x, v.y, h0, l0);
        split2(v.z, v.w, h1, l1);
        int cb = (h * 32 + 4 * j) * 2;       // byte col offset (8B aligned)
        *(uint2*)(sm_ + AS_HI + row * 144 + cb) = make_uint2(h0, h1);
        *(uint2*)(sm_ + AS_LO + row * 144 + cb) = make_uint2(l0, l1);
    }
}

// one 128x64x64 gemm, split-3 passes, accumulate into d
__device__ __forceinline__ void gemm_h(const char* sm_, int bslot,
                                       int ao, int bo, float d[8][4]) {
    #pragma unroll
    for (int ks = 0; ks < 4; ++ks) {
        const int ka = ks * 32;
        u32 ah0 = *(const u32*)(sm_ + AS_HI + ao + ka);
        u32 ah1 = *(const u32*)(sm_ + AS_HI + ao + ka + 1152);
        u32 ah2 = *(const u32*)(sm_ + AS_HI + ao + ka + 16);
        u32 ah3 = *(const u32*)(sm_ + AS_HI + ao + ka + 1152 + 16);
        u32 al0 = *(const u32*)(sm_ + AS_LO + ao + ka);
        u32 al1 = *(const u32*)(sm_ + AS_LO + ao + ka + 1152);
        u32 al2 = *(const u32*)(sm_ + AS_LO + ao + ka + 16);
        u32 al3 = *(const u32*)(sm_ + AS_LO + ao + ka + 1152 + 16);
        u32 bh[8][2], bl[8][2];
        #pragma unroll
        for (int nt = 0; nt < 8; ++nt) {
            bh[nt][0] = *(const u32*)(sm_ + bslot        + bo + nt * 1152 + ka);
            bh[nt][1] = *(const u32*)(sm_ + bslot        + bo + nt * 1152 + ka + 16);
            bl[nt][0] = *(const u32*)(sm_ + bslot + 9216 + bo + nt * 1152 + ka);
            bl[nt][1] = *(const u32*)(sm_ + bslot + 9216 + bo + nt * 1152 + ka + 16);
        }
        #pragma unroll
        for (int nt = 0; nt < 8; ++nt)
            hmma(d[nt][0], d[nt][1], d[nt][2], d[nt][3],
                 ah0, ah1, ah2, ah3, bh[nt][0], bh[nt][1]);
        #pragma unroll
        for (int nt = 0; nt < 8; ++nt)
            hmma(d[nt][0], d[nt][1], d[nt][2], d[nt][3],
                 ah0, ah1, ah2, ah3, bl[nt][0], bl[nt][1]);
        #pragma unroll
        for (int nt = 0; nt < 8; ++nt)
            hmma(d[nt][0], d[nt][1], d[nt][2], d[nt][3],
                 al0, al1, al2, al3, bh[nt][0], bh[nt][1]);
    }
}

// LN+SiLU on D fragments (rows rA=16w+g, rB=rA+8), split-store into A tiles
__device__ __forceinline__ void epi_ln(float d[8][4], char* sm_,
                                       int rowA_b, int rowB_b, int t2,
                                       const float* __restrict__ g,
                                       const float* __restrict__ be) {
    float sa = 0, qa = 0, sb = 0, qb = 0;
    #pragma unroll
    for (int nt = 0; nt < 8; ++nt) {
        sa += d[nt][0] + d[nt][1]; qa += d[nt][0] * d[nt][0] + d[nt][1] * d[nt][1];
        sb += d[nt][2] + d[nt][3]; qb += d[nt][2] * d[nt][2] + d[nt][3] * d[nt][3];
    }
    #pragma unroll
    for (int o = 1; o <= 2; o <<= 1) {
        sa += __shfl_xor_sync(0xffffffffu, sa, o);
        qa += __shfl_xor_sync(0xffffffffu, qa, o);
        sb += __shfl_xor_sync(0xffffffffu, sb, o);
        qb += __shfl_xor_sync(0xffffffffu, qb, o);
    }
    float mua = sa * (1.0f / 64.0f), mub = sb * (1.0f / 64.0f);
    float ra = rsqrtf(fmaxf(qa * (1.0f / 64.0f) - mua * mua, 0.0f) + 1e-5f);
    float rb = rsqrtf(fmaxf(qb * (1.0f / 64.0f) - mub * mub, 0.0f) + 1e-5f);
    #pragma unroll
    for (int nt = 0; nt < 8; ++nt) {
        int col = nt * 8 + t2;
        float2 gv = *(const float2*)(g + col);
        float2 bv = *(const float2*)(be + col);
        float x0 = (d[nt][0] - mua) * ra * gv.x + bv.x;
        float x1 = (d[nt][1] - mua) * ra * gv.y + bv.y;
        float y0 = (d[nt][2] - mub) * rb * gv.x + bv.x;
        float y1 = (d[nt][3] - mub) * rb * gv.y + bv.y;
        x0 = x0 / (1.0f + __expf(-x0));
        x1 = x1 / (1.0f + __expf(-x1));
        y0 = y0 / (1.0f + __expf(-y0));
        y1 = y1 / (1.0f + __expf(-y1));
        u32 hi, lo;
        split2(x0, x1, hi, lo);
        *(u32*)(sm_ + AS_HI + rowA_b + col * 2) = hi;
        *(u32*)(sm_ + AS_LO + rowA_b + col * 2) = lo;
        split2(y0, y1, hi, lo);
        *(u32*)(sm_ + AS_HI + rowB_b + col * 2) = hi;
        *(u32*)(sm_ + AS_LO + rowB_b + col * 2) = lo;
    }
}

__global__ __launch_bounds__(256, 2)
void mlp_kernel(const int*   __restrict__ species,
                const float* __restrict__ dist,
                const int*   __restrict__ senders,
                const int*   __restrict__ receivers,
                const float* __restrict__ g1, const float* __restrict__ be1,
                const float* __restrict__ b2,
                const float* __restrict__ g2, const float* __restrict__ be2,
                const float* __restrict__ b3)
{
    extern __shared__ __align__(16) char sm_[];
    int* spS = (int*)(sm_ + SPS_O);
    int* spR = (int*)(sm_ + SPR_O);

    const int tid  = threadIdx.x;
    const int w    = tid >> 5;
    const int lane = tid & 31;
    const int g    = lane >> 2;     // 0..7
    const int t2   = (lane & 3) * 2;
    const int base = blockIdx.x * T1;
    const int rA   = 16 * w + g;
    const int rB   = rA + 8;
    const int ao   = rA * 144 + t2 * 2;   // a0 byte offset (t*4)
    const int bo   = g  * 144 + t2 * 2;   // b0 byte offset within n-tile row
    const float4* dp = (const float4*)dist;

    // S0: B chunks 0,1; species idx; X chunk 0
    copyB(sm_, BSL0, 0, tid);
    copyB(sm_, BSL1, 1, tid);
    if (tid < T1) {
        spS[tid] = species[senders[base + tid]];
        spR[tid] = species[receivers[base + tid]];
    }
    splitX(sm_, dp, base, tid, 0);
    __syncthreads();

    // ---- stage 1: D init from species projections, then 2 k-chunks
    float d[8][4];
    {
        int ssa = spS[rA], sra = spR[rA], ssb = spS[rB], srb = spR[rB];
        #pragma unroll
        for (int nt = 0; nt < 8; ++nt) {
            int col = nt * 8 + t2;
            float2 s1 = *(const float2*)(SPb + ssa * 64 + col);
            float2 r1 = *(const float2*)(RPb + sra * 64 + col);
            float2 s2 = *(const float2*)(SPb + ssb * 64 + col);
            float2 r2 = *(const float2*)(RPb + srb * 64 + col);
            d[nt][0] = s1.x + r1.x; d[nt][1] = s1.y + r1.y;
            d[nt][2] = s2.x + r2.x; d[nt][3] = s2.y + r2.y;
        }
    }
    gemm_h(sm_, BSL0, ao, bo, d);
    __syncthreads();
    splitX(sm_, dp, base, tid, 1);
    __syncthreads();
    gemm_h(sm_, BSL1, ao, bo, d);
    __syncthreads();                 // all reads of A(X) done

    // E1 -> H1 into A tiles; W2 -> slot0
    epi_ln(d, sm_, rA * 144, rB * 144, t2, g1, be1);
    copyB(sm_, BSL0, 2, tid);
    __syncthreads();

    // ---- stage 2
    #pragma unroll
    for (int nt = 0; nt < 8; ++nt)
        d[nt][0] = d[nt][1] = d[nt][2] = d[nt][3] = 0.0f;
    gemm_h(sm_, BSL0, ao, bo, d);
    __syncthreads();                 // all reads of H1 done
    #pragma unroll
    for (int nt = 0; nt < 8; ++nt) { // + b2 before LN
        int col = nt * 8 + t2;
        float2 bb = *(const float2*)(b2 + col);
        d[nt][0] += bb.x; d[nt][1] += bb.y;
        d[nt][2] += bb.x; d[nt][3] += bb.y;
    }
    epi_ln(d, sm_, rA * 144, rB * 144, t2, g2, be2);
    copyB(sm_, BSL1, 3, tid);        // W3 m=0 -> slot1
    __syncthreads();

    // ---- stage 3: 5 m-chunks, double-buffered B slots
    float* fA = F_buf + (size_t)(base + rA) * 320;
    float* fB = F_buf + (size_t)(base + rB) * 320;
    for (int m = 0; m < 5; ++m) {
        int slot = (m & 1) ? BSL0 : BSL1;
        #pragma unroll
        for (int nt = 0; nt < 8; ++nt)
            d[nt][0] = d[nt][1] = d[nt][2] = d[nt][3] = 0.0f;
        gemm_h(sm_, slot, ao, bo, d);
        #pragma unroll
        for (int nt = 0; nt < 8; ++nt) {
            int col = m * 64 + nt * 8 + t2;
            float2 bb = *(const float2*)(b3 + col);
            *(float2*)(fA + col) = make_float2(d[nt][0] + bb.x, d[nt][1] + bb.y);
            *(float2*)(fB + col) = make_float2(d[nt][2] + bb.x, d[nt][3] + bb.y);
        }
        if (m < 4) {
            __syncthreads();         // all warps past gemm m (slot(m+1) idle)
            copyB(sm_, (m & 1) ? BSL1 : BSL0, 3 + m + 1, tid);
            __syncthreads();
        }
    }
}

// ---------------- wigner gather (round-11 validated, with prefetch)
__global__ __launch_bounds__(256)
void wigner_gather(const float* __restrict__ wig,
                   const float* __restrict__ env,
                   float* __restrict__ out)
{
    __shared__ ull wbp[8][25 * 8];
    const int tid  = threadIdx.x;
    const int lane = tid & 31;
    const int warp = tid >> 5;
    const int node = blockIdx.x * 8 + warp;
    if (node >= NNODES) return;

    ull acc[FULLC];
    #pragma unroll
    for (int f = 0; f < FULLC; ++f) acc[f] = 0ull;

    const int beg = d_offs[node];
    const int end = d_offs[node + 1];
    ull* wp = wbp[warp];

    const int f0 = (lane +  0) / 5,  m0 = (lane +  0) - 5 * f0;
    const int f1 = (lane + 32) / 5,  m1 = (lane + 32) - 5 * f1;
    const int f2 = (lane + 64) / 5,  m2 = (lane + 64) - 5 * f2;
    const int f3 = (lane + 96) / 5,  m3 = (lane + 96) - 5 * f3;

    float wrv0 = 0, wrv1 = 0, wrv2 = 0, wrv3 = 0, scv = 0;
    ull fr[5] = {0, 0, 0, 0, 0};

    auto load_raw = [&](int e) {
        scv = env[e] * 0.2f;
        const float* wr = wig + (size_t)e * (FULLC * MALL);
        wrv0 = wr[f0 * MALL + m0];
        wrv1 = wr[f1 * MALL + m1];
        wrv2 = wr[f2 * MALL + m2];
        if (lane < 29) wrv3 = wr[f3 * MALL + m3];
        const ull* fp = (const ull*)(F_buf + (size_t)e * 320 + 2 * lane);
        fr[0] = fp[0]; fr[1] = fp[32]; fr[2] = fp[64]; fr[3] = fp[96]; fr[4] = fp[128];
    };

    if (beg < end) load_raw(d_eids[beg]);

    for (int idx = beg; idx < end; ++idx) {
        wp[f0 * 8 + m0] = pack2(wrv0 * scv);
        wp[f1 * 8 + m1] = pack2(wrv1 * scv);
        wp[f2 * 8 + m2] = pack2(wrv2 * scv);
        if (lane < 29) wp[f3 * 8 + m3] = pack2(wrv3 * scv);
        ull fc0 = fr[0], fc1 = fr[1], fc2 = fr[2], fc3 = fr[3], fc4 = fr[4];
        __syncwarp();

        if (idx + 1 < end) load_raw(d_eids[idx + 1]);

        #pragma unroll
        for (int f = 0; f < FULLC; ++f) {
            ulonglong2 wA = *(const ulonglong2*)(wp + f * 8);
            ulonglong2 wB = *(const ulonglong2*)(wp + f * 8 + 2);
            ull w4 = wp[f * 8 + 4];
            ull r = acc[f];
            fma2(r, wA.x, fc0);
            fma2(r, wA.y, fc1);
            fma2(r, wB.x, fc2);
            fma2(r, wB.y, fc3);
            fma2(r, w4,   fc4);
            acc[f] = r;
        }
        __syncwarp();
    }

    float* ob = out + (size_t)node * 1600 + 2 * lane;
    #pragma unroll
    for (int f = 0; f < FULLC; ++f) {
        float2 rv = unpk(acc[f]);
        *(float2*)(ob + f * 64) = rv;
    }

    if (lane == 0) { d_cnt[node] = 0; d_cur[node] = 0; }
}

extern "C" void kernel_launch(void* const* d_in, const int* in_sizes, int n_in,
                              void* d_out, int out_size)
{
    const int*   species   = (const int*)  d_in[0];
    const float* dist      = (const float*)d_in[1];
    const int*   senders   = (const int*)  d_in[2];
    const int*   receivers = (const int*)  d_in[3];
    const float* wig       = (const float*)d_in[4];
    const float* env       = (const float*)d_in[5];
    const float* semb      = (const float*)d_in[6];
    const float* remb      = (const float*)d_in[7];
    const float* W1  = (const float*)d_in[8];
    const float* b1  = (const float*)d_in[9];
    const float* g1  = (const float*)d_in[10];
    const float* be1 = (const float*)d_in[11];
    const float* W2  = (const float*)d_in[12];
    const float* b2  = (const float*)d_in[13];
    const float* g2  = (const float*)d_in[14];
    const float* be2 = (const float*)d_in[15];
    const float* W3  = (const float*)d_in[16];
    const float* b3  = (const float*)d_in[17];
    float* out = (float*)d_out;

    cudaFuncSetAttribute(mlp_kernel,
                         cudaFuncAttributeMaxDynamicSharedMemorySize, SMB);

    const int SPBLK = (NSPEC * 64 + 255) / 256;
    bprep_kernel<<<8, 256>>>(W1, W2, W3);
    prep_kernel<<<SPBLK + (E_TOTAL + 255) / 256, 256>>>(receivers, semb, remb, W1, b1);
    scan_kernel<<<1, 1024>>>();
    fill_kernel<<<(E_TOTAL + 255) / 256, 256>>>(receivers);
    mlp_kernel<<<NTILES, 256, SMB>>>(
        species, dist, senders, receivers, g1, be1, b2, g2, be2, b3);
    wigner_gather<<<(NNODES + 7) / 8, 256>>>(wig, env, out);
}